// round 1
// baseline (speedup 1.0000x reference)
#include <cuda_runtime.h>
#include <math.h>

// Problem constants
#define B_   4
#define H_   16
#define NF_  32
#define P_   16
#define M_   257          // P*P + 1
#define S_   (NF_ * M_)   // 8224
#define D_   64
#define NTOK (B_ * H_ * S_)           // 526336 tokens per tensor
#define TBL  (NF_ * 17 * 17 * 15)     // 138720 cos/sin pairs

// cos/sin table: [frame][r][c][pair] -> (cos, sin). ~1.1 MB, L2 resident.
__device__ float2 g_cs[TBL];

// ---------------------------------------------------------------------------
// Precompute cos/sin from freqs (shape 32x17x17x30). Pairs share freq values:
// f[2p] == f[2p+1], so we store 15 entries per position.
// Double-precision sincos: freq args reach ~402 rad; fp32 fast reduction
// would lose ~1e-4 absolute accuracy.
// ---------------------------------------------------------------------------
__global__ void precompute_cs_kernel(const float* __restrict__ freqs) {
    int i = blockIdx.x * blockDim.x + threadIdx.x;
    if (i >= TBL) return;
    int pos  = i / 15;
    int pair = i - pos * 15;
    double f = (double)freqs[pos * 30 + 2 * pair];
    double s, c;
    sincos(f, &s, &c);
    g_cs[i] = make_float2((float)c, (float)s);
}

// ---------------------------------------------------------------------------
// Main RoPE kernel. One float4 (dims 4t..4t+3) per thread; 16 threads/token.
// Dims 0..29 rotated (15 interleaved pairs), dims 30..63 copied.
// Covers q (token ids [0, NTOK)) and k ([NTOK, 2*NTOK)) in one launch.
// Output layout: [q_out | k_out], each (B,H,S,D) contiguous.
// ---------------------------------------------------------------------------
__global__ void frame_rope_kernel(const float4* __restrict__ q,
                                  const float4* __restrict__ k,
                                  float4* __restrict__ out) {
    int gid  = blockIdx.x * blockDim.x + threadIdx.x;  // float4 index, < 2*NTOK*16
    int t    = gid & 15;        // chunk within token (dims 4t..4t+3)
    int tokg = gid >> 4;        // global token id across both tensors

    const float4* src;
    int tok;
    if (tokg < NTOK) { src = q; tok = tokg; }
    else             { src = k; tok = tokg - NTOK; }

    float4 v = src[tok * 16 + t];
    float4 o = v;

    if (t < 8) {
        // Position within sequence -> (frame, r, c) cell in the freq grid.
        int s     = tok % S_;          // layout (b,h,S,d): seq pos = tok % S
        int frame = s / M_;
        int m     = s - frame * M_;
        int r, c;
        if (m == 256) { r = 16; c = 16; }
        else          { r = m >> 4; c = m & 15; }
        int base = ((frame * 17 + r) * 17 + c) * 15;

        int p0 = 2 * t;                // pair index of (v.x, v.y)
        float2 cs0 = g_cs[base + p0];  // p0 <= 14 when t < 8 -> always rotated
        o.x = v.x * cs0.x - v.y * cs0.y;
        o.y = v.y * cs0.x + v.x * cs0.y;
        if (p0 + 1 < 15) {             // pair (v.z, v.w): rotated only for t < 7
            float2 cs1 = g_cs[base + p0 + 1];
            o.z = v.z * cs1.x - v.w * cs1.y;
            o.w = v.w * cs1.x + v.z * cs1.y;
        }
    }

    out[gid] = o;
}

extern "C" void kernel_launch(void* const* d_in, const int* in_sizes, int n_in,
                              void* d_out, int out_size) {
    const float* q     = (const float*)d_in[0];
    const float* k     = (const float*)d_in[1];
    const float* freqs = (const float*)d_in[2];

    precompute_cs_kernel<<<(TBL + 255) / 256, 256>>>(freqs);

    const int total_f4 = 2 * NTOK * 16;  // 16,842,752 -> 65,792 blocks of 256
    frame_rope_kernel<<<total_f4 / 256, 256>>>(
        (const float4*)q, (const float4*)k, (float4*)d_out);
}

// round 2
// speedup vs baseline: 1.0858x; 1.0858x over previous
#include <cuda_runtime.h>
#include <math.h>

// Problem constants
#define B_   4
#define H_   16
#define NF_  32
#define P_   16
#define M_   257          // P*P + 1
#define S_   (NF_ * M_)   // 8224
#define D_   64
#define NTOK (B_ * H_ * S_)   // 526336 tokens per tensor

// Separable cos/sin table: pairs 0-4 depend only on frame (32 values),
// pairs 5-9 only on r (17), pairs 10-14 only on c (17).
// Layout: [0,160)   = frame*5 + j      (axis 0)
//         [160,245) = 160 + r*5 + j    (axis 1)
//         [245,330) = 245 + c*5 + j    (axis 2)
#define TBL_SMALL 330
__device__ float2 g_cs[TBL_SMALL];

// ---------------------------------------------------------------------------
// Precompute 330 unique cos/sin pairs from freqs (32x17x17x30).
// freqs[f][r][c][d]: d in [0,10) depends on f; [10,20) on r; [20,30) on c.
// Adjacent dims repeat (f[2j]==f[2j+1]). Double sincos for range reduction
// accuracy (args reach ~402 rad).
// ---------------------------------------------------------------------------
__global__ void precompute_cs_kernel(const float* __restrict__ freqs) {
    int i = blockIdx.x * blockDim.x + threadIdx.x;
    if (i >= TBL_SMALL) return;
    float f;
    if (i < 160) {
        int frame = i / 5, j = i - frame * 5;
        f = freqs[((frame * 17 + 0) * 17 + 0) * 30 + 2 * j];
    } else if (i < 245) {
        int k = i - 160;
        int r = k / 5, j = k - r * 5;
        f = freqs[((0 * 17 + r) * 17 + 0) * 30 + 10 + 2 * j];
    } else {
        int k = i - 245;
        int c = k / 5, j = k - c * 5;
        f = freqs[((0 * 17 + 0) * 17 + c) * 30 + 20 + 2 * j];
    }
    double s, co;
    sincos((double)f, &s, &co);
    g_cs[i] = make_float2((float)co, (float)s);
}

__device__ __forceinline__ int cs_idx(int p, int frame, int r, int c) {
    if (p < 5)  return frame * 5 + p;
    if (p < 10) return 160 + r * 5 + (p - 5);
    return 245 + c * 5 + (p - 10);
}

// ---------------------------------------------------------------------------
// Main RoPE kernel. 8 threads per token; thread t handles float4 chunks
// t (dims 4t..4t+3, rotated) and t+8 (dims 32+4t.., pure copy).
// Two independent loads issued up front -> MLP_eff = 2.
// Covers q (tokens [0,NTOK)) and k ([NTOK, 2*NTOK)) in one launch.
// ---------------------------------------------------------------------------
__global__ void frame_rope_kernel(const float4* __restrict__ q,
                                  const float4* __restrict__ k,
                                  float4* __restrict__ out) {
    int gid  = blockIdx.x * blockDim.x + threadIdx.x;   // < 2*NTOK*8
    int t    = gid & 7;         // chunk id within token (0..7)
    int tokg = gid >> 3;        // global token id across both tensors

    const float4* src;
    int tok;
    if (tokg < NTOK) { src = q; tok = tokg; }
    else             { src = k; tok = tokg - NTOK; }

    const float4* base = src + tok * 16;
    // Front-batch both independent loads.
    float4 v0 = base[t];        // rotated half (dims 0..29 live here)
    float4 v1 = base[t + 8];    // pure copy half

    // Position -> (frame, r, c) in freq grid; audio token (m==256) -> (16,16).
    int s     = tok % S_;
    int frame = s / M_;
    int m     = s - frame * M_;
    int r, c;
    if (m == 256) { r = 16; c = 16; }
    else          { r = m >> 4; c = m & 15; }

    int p0 = 2 * t;             // pair covering (v0.x, v0.y); always < 15
    float2 cs0 = g_cs[cs_idx(p0, frame, r, c)];

    float4 o0;
    o0.x = v0.x * cs0.x - v0.y * cs0.y;
    o0.y = v0.y * cs0.x + v0.x * cs0.y;
    if (t < 7) {                // pair p0+1 covers (v0.z, v0.w)
        float2 cs1 = g_cs[cs_idx(p0 + 1, frame, r, c)];
        o0.z = v0.z * cs1.x - v0.w * cs1.y;
        o0.w = v0.w * cs1.x + v0.z * cs1.y;
    } else {                    // dims 30,31 are not rotated
        o0.z = v0.z;
        o0.w = v0.w;
    }

    float4* obase = out + tokg * 16;
    obase[t]     = o0;
    obase[t + 8] = v1;
}

extern "C" void kernel_launch(void* const* d_in, const int* in_sizes, int n_in,
                              void* d_out, int out_size) {
    const float* q     = (const float*)d_in[0];
    const float* k     = (const float*)d_in[1];
    const float* freqs = (const float*)d_in[2];

    precompute_cs_kernel<<<2, 192>>>(freqs);

    const int total_threads = 2 * NTOK * 8;   // 8,421,376 -> 32,896 blocks
    frame_rope_kernel<<<total_threads / 256, 256>>>(
        (const float4*)q, (const float4*)k, (float4*)d_out);
}

// round 3
// speedup vs baseline: 1.1043x; 1.0171x over previous
#include <cuda_runtime.h>
#include <math.h>

// Problem constants
#define B_   4
#define H_   16
#define NF_  32
#define P_   16
#define M_   257          // P*P + 1
#define S_   (NF_ * M_)   // 8224
#define D_   64
#define NTOK (B_ * H_ * S_)   // 526336 tokens per tensor

// Separable cos/sin table: pairs 0-4 depend only on frame (32 values),
// pairs 5-9 only on r (17), pairs 10-14 only on c (17).
// Layout: [0,160)   = frame*5 + j      (axis 0)
//         [160,245) = 160 + r*5 + j    (axis 1)
//         [245,330) = 245 + c*5 + j    (axis 2)
#define TBL_SMALL 330
__device__ float2 g_cs[TBL_SMALL];

// ---------------------------------------------------------------------------
// Precompute 330 unique cos/sin pairs. Range-reduce in double (2 DFMA,
// exact to ~1e-14 for |f| <= 402), then fast fp32 sincosf on [-pi, pi].
// Avoids the slow FP64 sincos path entirely.
// ---------------------------------------------------------------------------
__global__ void precompute_cs_kernel(const float* __restrict__ freqs) {
    int i = blockIdx.x * blockDim.x + threadIdx.x;
    if (i >= TBL_SMALL) return;
    float f;
    if (i < 160) {
        int frame = i / 5, j = i - frame * 5;
        f = freqs[((frame * 17 + 0) * 17 + 0) * 30 + 2 * j];
    } else if (i < 245) {
        int k = i - 160;
        int r = k / 5, j = k - r * 5;
        f = freqs[((0 * 17 + r) * 17 + 0) * 30 + 10 + 2 * j];
    } else {
        int k = i - 245;
        int c = k / 5, j = k - c * 5;
        f = freqs[((0 * 17 + 0) * 17 + c) * 30 + 20 + 2 * j];
    }
    const double TWO_PI  = 6.283185307179586476925286766559;
    const double INV_2PI = 0.15915494309189533576888376337251;
    double d  = (double)f;
    double kq = rint(d * INV_2PI);
    float  r  = (float)(d - kq * TWO_PI);   // reduced arg in [-pi, pi]
    float s, c;
    sincosf(r, &s, &c);
    g_cs[i] = make_float2(c, s);
}

__device__ __forceinline__ int cs_idx(int p, int frame, int r, int c) {
    if (p < 5)  return frame * 5 + p;
    if (p < 10) return 160 + r * 5 + (p - 5);
    return 245 + c * 5 + (p - 10);
}

// ---------------------------------------------------------------------------
// Main RoPE kernel. 8 threads per seq-position; thread t handles float4
// chunks t (rotated) and t+8 (copy) of BOTH the q token and the k token at
// the same (b,h,s). 4 independent loads front-batched (MLP=4); cs lookups
// amortized across q and k. Streaming load/store hints (single-use data).
// ---------------------------------------------------------------------------
__global__ void frame_rope_kernel(const float4* __restrict__ q,
                                  const float4* __restrict__ k,
                                  float4* __restrict__ out) {
    int gid = blockIdx.x * blockDim.x + threadIdx.x;   // < NTOK*8
    int t   = gid & 7;          // chunk id within token (0..7)
    int tok = gid >> 3;         // token id (same for q and k)

    const float4* qb = q + tok * 16;
    const float4* kb = k + tok * 16;
    // Front-batch all four independent loads.
    float4 q0 = __ldcs(qb + t);
    float4 q1 = __ldcs(qb + t + 8);
    float4 k0 = __ldcs(kb + t);
    float4 k1 = __ldcs(kb + t + 8);

    // Position -> (frame, r, c); audio token (m==256) -> (16,16).
    int s     = tok % S_;
    int frame = s / M_;
    int m     = s - frame * M_;
    int r, c;
    if (m == 256) { r = 16; c = 16; }
    else          { r = m >> 4; c = m & 15; }

    int p0 = 2 * t;             // pair covering (.x, .y); always < 15
    float2 cs0 = g_cs[cs_idx(p0, frame, r, c)];
    float2 cs1 = make_float2(1.0f, 0.0f);   // identity for dims 30,31
    if (t < 7) cs1 = g_cs[cs_idx(p0 + 1, frame, r, c)];

    float4 oq, ok;
    oq.x = q0.x * cs0.x - q0.y * cs0.y;
    oq.y = q0.y * cs0.x + q0.x * cs0.y;
    oq.z = q0.z * cs1.x - q0.w * cs1.y;
    oq.w = q0.w * cs1.x + q0.z * cs1.y;
    ok.x = k0.x * cs0.x - k0.y * cs0.y;
    ok.y = k0.y * cs0.x + k0.x * cs0.y;
    ok.z = k0.z * cs1.x - k0.w * cs1.y;
    ok.w = k0.w * cs1.x + k0.z * cs1.y;

    float4* oqb = out + tok * 16;
    float4* okb = out + (NTOK + tok) * 16;
    __stcs(oqb + t,     oq);
    __stcs(oqb + t + 8, q1);
    __stcs(okb + t,     ok);
    __stcs(okb + t + 8, k1);
}

extern "C" void kernel_launch(void* const* d_in, const int* in_sizes, int n_in,
                              void* d_out, int out_size) {
    const float* q     = (const float*)d_in[0];
    const float* k     = (const float*)d_in[1];
    const float* freqs = (const float*)d_in[2];

    precompute_cs_kernel<<<2, 192>>>(freqs);

    const int total_threads = NTOK * 8;   // 4,210,688 -> 16,448 blocks
    frame_rope_kernel<<<total_threads / 256, 256>>>(
        (const float4*)q, (const float4*)k, (float4*)d_out);
}

// round 4
// speedup vs baseline: 1.1336x; 1.0265x over previous
#include <cuda_runtime.h>
#include <math.h>

// Problem constants
#define B_   4
#define H_   16
#define NF_  32
#define P_   16
#define M_   257          // P*P + 1
#define S_   (NF_ * M_)   // 8224
#define D_   64
#define NTOK (B_ * H_ * S_)   // 526336 tokens per tensor

// Separable cos/sin table: pairs 0-4 depend only on frame (32 values),
// pairs 5-9 only on r (17), pairs 10-14 only on c (17).
// Layout: [0,160)   = frame*5 + j      (axis 0)
//         [160,245) = 160 + r*5 + j    (axis 1)
//         [245,330) = 245 + c*5 + j    (axis 2)
#define TBL_SMALL 330

__device__ __forceinline__ int cs_idx(int p, int frame, int r, int c) {
    if (p < 5)  return frame * 5 + p;
    if (p < 10) return 160 + r * 5 + (p - 5);
    return 245 + c * 5 + (p - 10);
}

// ---------------------------------------------------------------------------
// Fully fused kernel. Prologue: each block builds the 330-entry cos/sin
// table in shared memory (libm sincosf: ~2 ulp even at |x|~402 via internal
// extended-precision reduction; tolerance is 1e-3, so no FP64 needed).
// Mainloop: 8 threads per seq-position; thread t handles float4 chunks
// t (rotated) and t+8 (copy) of BOTH q and k tokens at the same (b,h,s).
// 4 independent streaming loads; cs lookups from smem, amortized over q+k.
// ---------------------------------------------------------------------------
__global__ __launch_bounds__(256) void frame_rope_fused(
        const float*  __restrict__ freqs,
        const float4* __restrict__ q,
        const float4* __restrict__ k,
        float4*       __restrict__ out) {
    __shared__ float2 s_cs[TBL_SMALL];

    // --- Table build (per block, amortized across concurrent blocks) ---
    for (int i = threadIdx.x; i < TBL_SMALL; i += 256) {
        float f;
        if (i < 160) {
            int frame = i / 5, j = i - frame * 5;
            f = freqs[((frame * 17 + 0) * 17 + 0) * 30 + 2 * j];
        } else if (i < 245) {
            int kk = i - 160;
            int r = kk / 5, j = kk - r * 5;
            f = freqs[((0 * 17 + r) * 17 + 0) * 30 + 10 + 2 * j];
        } else {
            int kk = i - 245;
            int c = kk / 5, j = kk - c * 5;
            f = freqs[((0 * 17 + 0) * 17 + c) * 30 + 20 + 2 * j];
        }
        float s, c;
        sincosf(f, &s, &c);
        s_cs[i] = make_float2(c, s);
    }
    __syncthreads();

    // --- Main body ---
    int gid = blockIdx.x * blockDim.x + threadIdx.x;   // < NTOK*8
    int t   = gid & 7;          // chunk id within token (0..7)
    int tok = gid >> 3;         // token id (same for q and k)

    const float4* qb = q + tok * 16;
    const float4* kb = k + tok * 16;
    // Front-batch all four independent loads (streaming: single-use data).
    float4 q0 = __ldcs(qb + t);
    float4 q1 = __ldcs(qb + t + 8);
    float4 k0 = __ldcs(kb + t);
    float4 k1 = __ldcs(kb + t + 8);

    // Position -> (frame, r, c); audio token (m==256) -> (16,16).
    int s     = tok % S_;
    int frame = s / M_;
    int m     = s - frame * M_;
    int r, c;
    if (m == 256) { r = 16; c = 16; }
    else          { r = m >> 4; c = m & 15; }

    int p0 = 2 * t;             // pair covering (.x, .y); always < 15
    float2 cs0 = s_cs[cs_idx(p0, frame, r, c)];
    float2 cs1 = make_float2(1.0f, 0.0f);   // identity for dims 30,31
    if (t < 7) cs1 = s_cs[cs_idx(p0 + 1, frame, r, c)];

    float4 oq, ok;
    oq.x = q0.x * cs0.x - q0.y * cs0.y;
    oq.y = q0.y * cs0.x + q0.x * cs0.y;
    oq.z = q0.z * cs1.x - q0.w * cs1.y;
    oq.w = q0.w * cs1.x + q0.z * cs1.y;
    ok.x = k0.x * cs0.x - k0.y * cs0.y;
    ok.y = k0.y * cs0.x + k0.x * cs0.y;
    ok.z = k0.z * cs1.x - k0.w * cs1.y;
    ok.w = k0.w * cs1.x + k0.z * cs1.y;

    float4* oqb = out + tok * 16;
    float4* okb = out + (NTOK + tok) * 16;
    __stcs(oqb + t,     oq);
    __stcs(oqb + t + 8, q1);
    __stcs(okb + t,     ok);
    __stcs(okb + t + 8, k1);
}

extern "C" void kernel_launch(void* const* d_in, const int* in_sizes, int n_in,
                              void* d_out, int out_size) {
    const float* q     = (const float*)d_in[0];
    const float* k     = (const float*)d_in[1];
    const float* freqs = (const float*)d_in[2];

    const int total_threads = NTOK * 8;   // 4,210,688 -> 16,448 blocks
    frame_rope_fused<<<total_threads / 256, 256>>>(
        freqs, (const float4*)q, (const float4*)k, (float4*)d_out);
}